// round 11
// baseline (speedup 1.0000x reference)
#include <cuda_runtime.h>
#include <cstdint>

#define NBATCH 8
#define CHN 8
#define HH 512
#define HB 256
#define RSQ2 0.70710678118654752440f
#define SQ2F 1.41421356237309504880f
#define SECSZ (NBATCH*CHN*HB*HB)   /* 4194304 */

// ---------------- scratch ----------------
__device__ float g_Sx [NBATCH*HH*HH];
__device__ float g_T1 [NBATCH*HH*HH];
__device__ float g_B  [NBATCH*HH*HH];
__device__ float g_Sd [NBATCH*HH*HH];
__device__ float g_cp [NBATCH*HB*HB];
__device__ float g_Sp0[NBATCH*HB*HH];
__device__ float g_Sp1[NBATCH*HB*HH];
__device__ float g_F1 [NBATCH*HB*HH];
__device__ float g_Sx0[NBATCH*HB*HH];
__device__ float g_F2 [NBATCH*HB*HH];
__device__ float g_Sxx[NBATCH*HB*HH];
__device__ float g_SP0[NBATCH*HB*HB];
__device__ float g_SP1[NBATCH*HB*HB];
__device__ float g_G1 [NBATCH*HB*HB];
__device__ float g_Se0[NBATCH*HB*HB];
__device__ float g_G2 [NBATCH*HB*HB];

// ---------------- software grid barrier ----------------
__device__ unsigned int g_bar_count = 0;
__device__ unsigned int g_bar_phase = 0;

__device__ __forceinline__ void gsync() {
    __syncthreads();
    if (threadIdx.x == 0) {
        unsigned int gen = *((volatile unsigned int*)&g_bar_phase);
        __threadfence();
        unsigned int t = atomicAdd(&g_bar_count, 1u);
        if (t == gridDim.x - 1u) {
            g_bar_count = 0u;
            __threadfence();
            atomicExch(&g_bar_phase, gen + 1u);
        } else {
            while (*((volatile unsigned int*)&g_bar_phase) == gen) { }
            __threadfence();
        }
    }
    __syncthreads();
}

// ---- fused separable 12-tap conv on a 32x32 tile, smem-staged -------------
// SM layout: ti = SM[0 .. 44*45), tc = SM[1980 .. 1980+44*33)
template<int W, bool QPER, int CL>
__device__ __forceinline__ void conv_tile(const float* __restrict__ inb,
                                          const float* __restrict__ f,
                                          int r0, int s0, int tid,
                                          float* SM, float (&F)[4]) {
    float* ti = SM;             // [44][45]
    float* tc = SM + 1980;      // [44][33]
    float fv[12];
#pragma unroll
    for (int k = 0; k < 12; k++) fv[k] = f[k];
    constexpr int LSH = (W == 512) ? 9 : 8;
    for (int e = tid; e < 44 * 44; e += 256) {
        int lt = e / 44, ls = e - lt * 44;
        int t = r0 + lt - 6;
        int s = s0 + ls - 6;
        int sr, sc;
        if (QPER) {
            if ((unsigned)t < 256u) { sr = t; sc = s & (W - 1); }
            else { sr = t & 255; sc = (s + (W / 2)) & (W - 1); }
        } else { sr = t & 255; sc = s & (W - 1); }
        ti[lt * 45 + ls] = inb[(sr << LSH) + sc];
    }
    __syncthreads();
    for (int e = tid; e < 44 * 32; e += 256) {
        int lt = e >> 5, lo = e & 31;
        float acc = 0.f;
#pragma unroll
        for (int b = 0; b < 12; b++) acc += fv[b] * ti[lt * 45 + lo + b + (6 - CL)];
        tc[lt * 33 + lo] = acc;
    }
    __syncthreads();
    int w = tid >> 5, l = tid & 31;
#pragma unroll
    for (int k = 0; k < 4; k++) {
        int li = w + (k << 3);
        float acc = 0.f;
#pragma unroll
        for (int a = 0; a < 12; a++) acc += fv[a] * tc[(li + a + (6 - CL)) * 33 + l];
        F[k] = acc;
    }
}

// ---------------- the one persistent kernel --------------------------------
extern "C" __global__ void __launch_bounds__(256)
kall(const float* __restrict__ X, const float* __restrict__ h,
     const float* __restrict__ g, const float* __restrict__ f,
     float* __restrict__ out) {
    __shared__ float SM[4224];          // 16.9KB union for all stages
    int tid = threadIdx.x;

    // ================= stage 1: ksumrow (2 rows per block-iter) ============
    {
        float hv[9];
#pragma unroll
        for (int k = 0; k < 9; k++) hv[k] = h[k];
        int sub = tid >> 7, t = tid & 127;
        for (int p = blockIdx.x; p < (NBATCH * HH) / 2; p += gridDim.x) {
            int row = (p << 1) + sub;
            int n = row >> 9;
            const float4* xb = reinterpret_cast<const float4*>(X)
                + (size_t)n * CHN * 65536 + (size_t)(row & 511) * 128 + t;
            float4 a = xb[0];
#pragma unroll
            for (int c = 1; c < CHN; c++) {
                float4 v = xb[(size_t)c * 65536];
                a.x += v.x; a.y += v.y; a.z += v.z; a.w += v.w;
            }
            reinterpret_cast<float4*>(SM)[sub * 128 + t] = a;
            reinterpret_cast<float4*>(g_Sx)[(size_t)row * 128 + t] = a;
            __syncthreads();
            float4 o; float* op = &o.x;
#pragma unroll
            for (int k = 0; k < 4; k++) {
                int j = 4 * t + k;
                float acc = 0.f;
#pragma unroll
                for (int a2 = 0; a2 < 9; a2++)
                    acc += hv[a2] * SM[sub * 512 + ((j + a2 - 4) & 511)];
                op[k] = acc;
            }
            reinterpret_cast<float4*>(g_T1)[(size_t)row * 128 + t] = o;
            __syncthreads();
        }
    }
    gsync();

    // ================= stage 2: kpool =======================================
    {
        float hv[9];
#pragma unroll
        for (int k = 0; k < 9; k++) hv[k] = h[k];
        for (int idx = blockIdx.x * 256 + tid; idx < NBATCH * HB * HB;
             idx += gridDim.x * 256) {
            int n = idx >> 16;
            int rem = idx & 65535;
            int p = rem >> 8, q = rem & 255;
            const float* T = g_T1 + ((size_t)n << 18);
            float acc = 0.f;
#pragma unroll
            for (int a = 0; a < 9; a++) {
                int r0 = ((2 * p + a - 4) & 511) << 9;
                int r1 = ((2 * p + 1 + a - 4) & 511) << 9;
                float2 t0 = *reinterpret_cast<const float2*>(T + r0 + 2 * q);
                float2 t1 = *reinterpret_cast<const float2*>(T + r1 + 2 * q);
                acc += hv[a] * (t0.x + t0.y + t1.x + t1.y);
            }
            acc *= 0.25f;
            g_cp[idx] = acc;
            size_t base = (size_t)(n * CHN) * 65536 + rem;
#pragma unroll
            for (int c = 0; c < CHN; c++) out[base + (size_t)c * 65536] = acc;
        }
    }
    gsync();

    // ================= stage 3: kBSd ========================================
    {
        float gv[7];
#pragma unroll
        for (int a = 0; a < 7; a++) gv[a] = g[a];
        for (int idx = blockIdx.x * 256 + tid; idx < NBATCH * HH * HH;
             idx += gridDim.x * 256) {
            int n = idx >> 18;
            int i = (idx >> 9) & 511, j = idx & 511;
            const float* cpb = g_cp + ((size_t)n << 16);
            float gr[4], gc[4];
            int ir[4], jc[4];
            if (i & 1) {
                gr[0] = gv[0]; gr[1] = gv[2]; gr[2] = gv[4]; gr[3] = gv[6];
                ir[0] = ((i - 3) & 511) >> 1; ir[1] = ((i - 1) & 511) >> 1;
                ir[2] = ((i + 1) & 511) >> 1; ir[3] = ((i + 3) & 511) >> 1;
            } else {
                gr[0] = gv[1]; gr[1] = gv[3]; gr[2] = gv[5]; gr[3] = 0.f;
                ir[0] = ((i - 2) & 511) >> 1; ir[1] = i >> 1;
                ir[2] = ((i + 2) & 511) >> 1; ir[3] = ir[0];
            }
            if (j & 1) {
                gc[0] = gv[0]; gc[1] = gv[2]; gc[2] = gv[4]; gc[3] = gv[6];
                jc[0] = ((j - 3) & 511) >> 1; jc[1] = ((j - 1) & 511) >> 1;
                jc[2] = ((j + 1) & 511) >> 1; jc[3] = ((j + 3) & 511) >> 1;
            } else {
                gc[0] = gv[1]; gc[1] = gv[3]; gc[2] = gv[5]; gc[3] = 0.f;
                jc[0] = ((j - 2) & 511) >> 1; jc[1] = j >> 1;
                jc[2] = ((j + 2) & 511) >> 1; jc[3] = jc[0];
            }
            float acc = 0.f;
#pragma unroll
            for (int a = 0; a < 4; a++) {
                const float* rowp = cpb + (ir[a] << 8);
                float inner = gc[0] * rowp[jc[0]] + gc[1] * rowp[jc[1]]
                            + gc[2] * rowp[jc[2]] + gc[3] * rowp[jc[3]];
                acc += gr[a] * inner;
            }
            float Bs = 8.f * acc;
            g_B[idx] = Bs;
            g_Sd[idx] = g_Sx[idx] - 8.f * Bs;
        }
    }
    gsync();

    // ================= stage 4: remap1 (tiled) ==============================
    for (int tt = blockIdx.x; tt < 16 * 8 * NBATCH; tt += gridDim.x) {
        int n = tt >> 7;
        int rem = tt & 127;
        int r0 = (rem >> 4) << 5;       // 0..7 -> 0..224
        int s0 = (rem & 15) << 5;       // 0..15 -> 0..480
        const float* Sd = g_Sd + ((size_t)n << 18);
        int tbase = (r0 - s0 - 31) & 511;
        int vbase = (r0 + s0) & 511;
#pragma unroll
        for (int it = 0; it < 16; it++) {
            int e = (it << 8) + tid;
            int lr = e >> 6, lc = e & 63;
            SM[lr * 66 + lc] = Sd[(((tbase + lr) & 511) << 9) + ((vbase + lc) & 511)];
        }
        __syncthreads();
        int w = tid >> 5, l = tid & 31;
        int s = s0 + l;
#pragma unroll
        for (int k = 0; k < 4; k++) {
            int dr = w + (k << 3);
            int r = r0 + dr;
            int ti = 31 + dr - l;
            int vi = dr + l;
            size_t o = ((size_t)n << 17) + ((size_t)r << 9) + s;
            g_Sp0[o] = SM[ti * 66 + vi];
            g_Sp1[o] = SM[ti * 66 + vi + 1];
        }
        __syncthreads();
    }
    gsync();

    // ================= stage 5: convq1 ======================================
    for (int tt = blockIdx.x; tt < 16 * 8 * NBATCH; tt += gridDim.x) {
        int n = tt >> 7;
        int rem = tt & 127;
        int r0 = (rem >> 4) << 5;
        int s0 = (rem & 15) << 5;
        float F[4];
        conv_tile<512, true, 6>(g_Sp1 + ((size_t)n << 17), f, r0, s0, tid, SM, F);
        int w = tid >> 5, l = tid & 31;
        size_t base = ((size_t)n << 17) + s0 + l;
#pragma unroll
        for (int k = 0; k < 4; k++) {
            size_t o = base + ((size_t)(r0 + w + (k << 3)) << 9);
            g_F1[o] = F[k];
            g_Sx0[o] = (g_Sp0[o] - 8.f * F[k]) * RSQ2;
        }
        __syncthreads();
    }
    gsync();

    // ================= stage 6: convq2 ======================================
    for (int tt = blockIdx.x; tt < 16 * 8 * NBATCH; tt += gridDim.x) {
        int n = tt >> 7;
        int rem = tt & 127;
        int r0 = (rem >> 4) << 5;
        int s0 = (rem & 15) << 5;
        float F[4];
        conv_tile<512, true, 5>(g_Sx0 + ((size_t)n << 17), f, r0, s0, tid, SM, F);
        int w = tid >> 5, l = tid & 31;
        size_t base = ((size_t)n << 17) + s0 + l;
#pragma unroll
        for (int k = 0; k < 4; k++) {
            size_t o = base + ((size_t)(r0 + w + (k << 3)) << 9);
            g_F2[o] = F[k];
            g_Sxx[o] = g_Sx0[o] - SQ2F * g_Sp1[o] - 8.f * F[k];
        }
        __syncthreads();
    }
    gsync();

    // ================= stage 7: remap2 (tiled) ==============================
    for (int tt = blockIdx.x; tt < 8 * 8 * NBATCH; tt += gridDim.x) {
        int n = tt >> 6;
        int rem = tt & 63;
        int i0 = (rem >> 3) << 5;
        int j0 = (rem & 7) << 5;
        const float* Sxx = g_Sxx + ((size_t)n << 17);
        int w = tid >> 5, l = tid & 31;
        int S = i0 + j0;
        if (S == 224) {                 // straddle band: per-element slow path
#pragma unroll
            for (int k = 0; k < 4; k++) {
                int i = i0 + w + (k << 3), j = j0 + l;
                int ipj = i + j;
                int u = (j - i + ((ipj >= 256) ? 256 : 0)) & 511;
                int I1 = (ipj + 1) & 255;
                int s1 = (ipj == 255) ? (2 * j + 1) : u;
                size_t o = ((size_t)n << 16) + ((size_t)i << 8) + j;
                g_SP0[o] = Sxx[((ipj & 255) << 9) + u];
                g_SP1[o] = Sxx[(I1 << 9) + s1];
            }
            continue;
        }
        int d0 = (S >= 256) ? 256 : 0;
        int Ibase = S & 255;
        int ubase = (j0 - i0 - 31 + d0) & 511;
#pragma unroll
        for (int it = 0; it < 16; it++) {
            int e = (it << 8) + tid;
            int lr = e >> 6, lc = e & 63;
            SM[lr * 66 + lc] = Sxx[((Ibase + lr) << 9) + ((ubase + lc) & 511)];
        }
        __syncthreads();
        int j = j0 + l;
#pragma unroll
        for (int k = 0; k < 4; k++) {
            int di = w + (k << 3);
            int i = i0 + di;
            int lr = di + l;
            int lc = l - di + 31;
            size_t o = ((size_t)n << 16) + ((size_t)i << 8) + j;
            g_SP0[o] = SM[lr * 66 + lc];
            g_SP1[o] = SM[(lr + 1) * 66 + lc];
        }
        __syncthreads();
    }
    gsync();

    // ================= stage 8: convp1 ======================================
    for (int tt = blockIdx.x; tt < 8 * 8 * NBATCH; tt += gridDim.x) {
        int n = tt >> 6;
        int rem = tt & 63;
        int r0 = (rem >> 3) << 5;
        int s0 = (rem & 7) << 5;
        float F[4];
        conv_tile<256, false, 6>(g_SP1 + ((size_t)n << 16), f, r0, s0, tid, SM, F);
        int w = tid >> 5, l = tid & 31;
        size_t base = ((size_t)n << 16) + s0 + l;
#pragma unroll
        for (int k = 0; k < 4; k++) {
            size_t o = base + ((size_t)(r0 + w + (k << 3)) << 8);
            g_G1[o] = F[k];
            g_Se0[o] = (g_SP0[o] - 16.f * F[k]) * RSQ2;
        }
        __syncthreads();
    }
    gsync();

    // ================= stage 9: convp2 ======================================
    for (int tt = blockIdx.x; tt < 8 * 8 * NBATCH; tt += gridDim.x) {
        int n = tt >> 6;
        int rem = tt & 63;
        int r0 = (rem >> 3) << 5;
        int s0 = (rem & 7) << 5;
        float F[4];
        conv_tile<256, false, 5>(g_Se0 + ((size_t)n << 16), f, r0, s0, tid, SM, F);
        int w = tid >> 5, l = tid & 31;
        size_t base = ((size_t)n << 16) + s0 + l;
#pragma unroll
        for (int k = 0; k < 4; k++) {
            size_t o = base + ((size_t)(r0 + w + (k << 3)) << 8);
            g_G2[o] = F[k];
        }
        __syncthreads();
    }
    gsync();

    // ================= stage 10: final combine (j-pair vectorized) =========
    for (int idx = blockIdx.x * 256 + tid; idx < (NBATCH << 15);
         idx += gridDim.x * 256) {
        int n = idx >> 15;
        int rem = idx & 32767;
        int i = rem >> 7, jp = rem & 127;
        int j = jp << 1;

        const float* B  = g_B  + ((size_t)n << 18);
        const float* F1 = g_F1 + ((size_t)n << 17);
        const float* F2 = g_F2 + ((size_t)n << 17);
        size_t gidx = ((size_t)n << 16) + ((size_t)i << 8) + j;
        float2 g1v = *reinterpret_cast<const float2*>(g_G1 + gidx);
        float2 g2v = *reinterpret_cast<const float2*>(g_G2 + gidx);

        int rowE = 2 * i, rowO = 2 * i + 1;
        int xiE = rowE << 9, xiO = rowO << 9;
        int c4 = jp << 2;
        float4 Be = *reinterpret_cast<const float4*>(B + xiE + c4);
        float4 Bo = *reinterpret_cast<const float4*>(B + xiO + c4);
        float  Box = B[xiO + ((c4 + 4) & 511)];

        float K0[2], K1[2], K2[2], K3[2];
#pragma unroll
        for (int jj = 0; jj < 2; jj++) {
            int jv = j + jj;
            int ipj = i + jv;
            int d0 = (ipj >= 256) ? 256 : 0;
            int u  = (jv - i + d0) & 511;
            int r  = ipj & 255;
            int r1 = (ipj + 1) & 255;
            int s1 = (ipj == 255) ? (2 * jv + 1) : u;
            float f1a = F1[(r  << 9) + u];
            float f1b = F1[(r1 << 9) + s1];
            float f2a = F2[(r  << 9) + u];
            float f2b = F2[(r1 << 9) + s1];
            float b00 = jj ? Be.z : Be.x;
            float b01 = jj ? Be.w : Be.y;
            float b10 = jj ? Bo.w : Bo.y;
            float b11 = jj ? Box  : Bo.z;
            float g1 = jj ? g1v.y : g1v.x;
            float g2 = jj ? g2v.y : g2v.x;
            K0[jj] = 0.5f * (b00 + f1a) + g1 * RSQ2;
            K1[jj] = b01 - (f2a + g1) * RSQ2;
            K2[jj] = b10 + f1b - g2;
            K3[jj] = -2.f * b11 + SQ2F * f2b - g2;
        }

        const float* Xn = X + ((size_t)(n * CHN) << 18);
        size_t obase = (size_t)(n * CHN) * 65536 + ((size_t)i << 8) + j;
        int xoxc = (c4 + 4) & 511;
#pragma unroll
        for (int c = 0; c < CHN; c++) {
            const float* Xc = Xn + ((size_t)c << 18);
            float4 Xe = *reinterpret_cast<const float4*>(Xc + xiE + c4);
            float4 Xo = *reinterpret_cast<const float4*>(Xc + xiO + c4);
            float  Xox = Xc[xiO + xoxc];
            size_t o = obase + (size_t)c * 65536;
            *reinterpret_cast<float2*>(out + (size_t)SECSZ * 1 + o) =
                make_float2(-Xo.y + K2[0], -Xo.w + K2[1]);
            *reinterpret_cast<float2*>(out + (size_t)SECSZ * 2 + o) =
                make_float2(0.5f * Xe.x - K0[0], 0.5f * Xe.z - K0[1]);
            *reinterpret_cast<float2*>(out + (size_t)SECSZ * 3 + o) =
                make_float2(2.f * Xo.z + K3[0], 2.f * Xox + K3[1]);
            *reinterpret_cast<float2*>(out + (size_t)SECSZ * 4 + o) =
                make_float2(-Xe.y + K1[0], -Xe.w + K1[1]);
        }
    }
}

// ---------------- launch: ONE persistent kernel ----------------------------
extern "C" void kernel_launch(void* const* d_in, const int* in_sizes, int n_in,
                              void* d_out, int out_size) {
    const float* X = (const float*)d_in[0];
    const float* h = (const float*)d_in[1];
    const float* g = (const float*)d_in[2];
    const float* f = (const float*)d_in[3];
    float* out = (float*)d_out;

    int dev = 0;
    cudaGetDevice(&dev);
    int nsm = 0;
    cudaDeviceGetAttribute(&nsm, cudaDevAttrMultiProcessorCount, dev);
    int nb = 0;
    cudaOccupancyMaxActiveBlocksPerMultiprocessor(&nb, kall, 256, 0);
    if (nb < 1) nb = 1;
    if (nsm < 1) nsm = 1;
    int grid = nb * nsm;

    kall<<<grid, 256>>>(X, h, g, f, out);
}

// round 12
// speedup vs baseline: 1.2377x; 1.2377x over previous
#include <cuda_runtime.h>
#include <cstdint>

#define NBATCH 8
#define CHN 8
#define HH 512
#define HB 256
#define RSQ2 0.70710678118654752440f
#define SQ2F 1.41421356237309504880f
#define SECSZ (NBATCH*CHN*HB*HB)   /* 4194304 */
#define NSTREAM 2
#define NB_PER (NBATCH/NSTREAM)    /* 4 */

#if defined(__CUDA_ARCH__) && __CUDA_ARCH__ >= 900
#define PDL_SYNC() cudaGridDependencySynchronize()
#else
#define PDL_SYNC()
#endif

// ---------------- scratch ----------------
__device__ float g_Sx [NBATCH*HH*HH];
__device__ float g_T1 [NBATCH*HH*HH];
__device__ float g_B  [NBATCH*HH*HH];
__device__ float g_Sd [NBATCH*HH*HH];
__device__ float g_cp [NBATCH*HB*HB];
__device__ float g_Sp0[NBATCH*HB*HH];
__device__ float g_Sp1[NBATCH*HB*HH];
__device__ float g_F1 [NBATCH*HB*HH];
__device__ float g_Sx0[NBATCH*HB*HH];
__device__ float g_F2 [NBATCH*HB*HH];
__device__ float g_Sxx[NBATCH*HB*HH];
__device__ float g_SP0[NBATCH*HB*HB];
__device__ float g_SP1[NBATCH*HB*HB];
__device__ float g_G1 [NBATCH*HB*HB];
__device__ float g_Se0[NBATCH*HB*HB];
__device__ float g_G2 [NBATCH*HB*HB];

// ---------------- streams (host-side, created at static init) ----------------
static cudaStream_t g_s[NSTREAM];
static cudaEvent_t g_evRoot, g_evEnd[NSTREAM];
static struct StreamInit {
    StreamInit() {
        for (int k = 0; k < NSTREAM; k++) {
            cudaStreamCreateWithFlags(&g_s[k], cudaStreamNonBlocking);
            cudaEventCreateWithFlags(&g_evEnd[k], cudaEventDisableTiming);
        }
        cudaEventCreateWithFlags(&g_evRoot, cudaEventDisableTiming);
    }
} g_streamInit;

// ---------------- kernels (all take n0 = batch offset) ----------------------

// 1) fused: Sx = channel-sum of X  AND  T1 = row conv(h, per) of Sx.
__global__ void ksumrow(const float* __restrict__ X, const float* __restrict__ h,
                        int n0) {
    __shared__ float srow[HH];
    int row = blockIdx.x + (n0 << 9);
    int n = row >> 9;
    int t = threadIdx.x;
    const float4* xb = reinterpret_cast<const float4*>(X)
                       + (size_t)n * CHN * 65536 + (size_t)(row & 511) * 128 + t;
    float4 a = xb[0];
#pragma unroll
    for (int c = 1; c < CHN; c++) {
        float4 v = xb[(size_t)c * 65536];
        a.x += v.x; a.y += v.y; a.z += v.z; a.w += v.w;
    }
    reinterpret_cast<float4*>(srow)[t] = a;
    reinterpret_cast<float4*>(g_Sx)[(size_t)row * 128 + t] = a;
    __syncthreads();
    float hv[9];
#pragma unroll
    for (int k = 0; k < 9; k++) hv[k] = h[k];
    float4 o;
    float* op = &o.x;
#pragma unroll
    for (int k = 0; k < 4; k++) {
        int j = 4 * t + k;
        float acc = 0.f;
#pragma unroll
        for (int a2 = 0; a2 < 9; a2++) acc += hv[a2] * srow[(j + a2 - 4) & 511];
        op[k] = acc;
    }
    reinterpret_cast<float4*>(g_T1)[(size_t)row * 128 + t] = o;
}

// 3) col pass of conv h + 2x2 avgpool -> cp ; also write output section 0
__global__ void kpool(const float* __restrict__ h, float* __restrict__ out,
                      int n0) {
    float hv[9];
#pragma unroll
    for (int k = 0; k < 9; k++) hv[k] = h[k];
    PDL_SYNC();
    int idx = blockIdx.x * blockDim.x + threadIdx.x + (n0 << 16);
    int n = idx >> 16;
    int rem = idx & 65535;
    int p = rem >> 8, q = rem & 255;
    const float* T = g_T1 + ((size_t)n << 18);
    float acc = 0.f;
#pragma unroll
    for (int a = 0; a < 9; a++) {
        int r0 = ((2 * p + a - 4) & 511) << 9;
        int r1 = ((2 * p + 1 + a - 4) & 511) << 9;
        float2 t0 = *reinterpret_cast<const float2*>(T + r0 + 2 * q);
        float2 t1 = *reinterpret_cast<const float2*>(T + r1 + 2 * q);
        acc += hv[a] * (t0.x + t0.y + t1.x + t1.y);
    }
    acc *= 0.25f;
    g_cp[idx] = acc;
    size_t base = (size_t)(n * CHN) * 65536 + rem;
#pragma unroll
    for (int c = 0; c < CHN; c++) out[base + (size_t)c * 65536] = acc;
}

// 4) B = 8*conv_per(up2(cp), g x g) polyphase, parity-specialized; Sd = Sx - 8*B
__global__ void kBSd(const float* __restrict__ g, int n0) {
    float gv[7];
#pragma unroll
    for (int a = 0; a < 7; a++) gv[a] = g[a];
    PDL_SYNC();
    int idx = blockIdx.x * blockDim.x + threadIdx.x + (n0 << 18);
    int n = idx >> 18;
    int i = (idx >> 9) & 511, j = idx & 511;
    const float* cpb = g_cp + ((size_t)n << 16);

    float gr[4], gc[4];
    int ir[4], jc[4];
    if (i & 1) {
        gr[0] = gv[0]; gr[1] = gv[2]; gr[2] = gv[4]; gr[3] = gv[6];
        ir[0] = ((i - 3) & 511) >> 1; ir[1] = ((i - 1) & 511) >> 1;
        ir[2] = ((i + 1) & 511) >> 1; ir[3] = ((i + 3) & 511) >> 1;
    } else {
        gr[0] = gv[1]; gr[1] = gv[3]; gr[2] = gv[5]; gr[3] = 0.f;
        ir[0] = ((i - 2) & 511) >> 1; ir[1] = i >> 1;
        ir[2] = ((i + 2) & 511) >> 1; ir[3] = ir[0];
    }
    if (j & 1) {
        gc[0] = gv[0]; gc[1] = gv[2]; gc[2] = gv[4]; gc[3] = gv[6];
        jc[0] = ((j - 3) & 511) >> 1; jc[1] = ((j - 1) & 511) >> 1;
        jc[2] = ((j + 1) & 511) >> 1; jc[3] = ((j + 3) & 511) >> 1;
    } else {
        gc[0] = gv[1]; gc[1] = gv[3]; gc[2] = gv[5]; gc[3] = 0.f;
        jc[0] = ((j - 2) & 511) >> 1; jc[1] = j >> 1;
        jc[2] = ((j + 2) & 511) >> 1; jc[3] = jc[0];
    }
    float acc = 0.f;
#pragma unroll
    for (int a = 0; a < 4; a++) {
        const float* rowp = cpb + (ir[a] << 8);
        float inner = gc[0] * rowp[jc[0]] + gc[1] * rowp[jc[1]]
                    + gc[2] * rowp[jc[2]] + gc[3] * rowp[jc[3]];
        acc += gr[a] * inner;
    }
    float Bs = 8.f * acc;
    g_B[idx] = Bs;
    g_Sd[idx] = g_Sx[idx] - 8.f * Bs;
}

// 5) TILED diagonal remap: Sp0[r,s]=Sd[(r-s)%512,(r+s)%512]; Sp1: col+1.
__global__ void kremap1t(int n0) {
    __shared__ float tile[64][66];
    PDL_SYNC();
    int n = blockIdx.z + n0;
    int r0 = blockIdx.y << 5;
    int s0 = blockIdx.x << 5;
    const float* Sd = g_Sd + ((size_t)n << 18);
    int tbase = (r0 - s0 - 31) & 511;
    int vbase = (r0 + s0) & 511;
    int tid = threadIdx.x;
#pragma unroll
    for (int it = 0; it < 16; it++) {
        int lr = (it << 2) + (tid >> 6);
        int lc = tid & 63;
        tile[lr][lc] = Sd[(((tbase + lr) & 511) << 9) + ((vbase + lc) & 511)];
    }
    __syncthreads();
    int w = tid >> 5, l = tid & 31;
    int s = s0 + l;
#pragma unroll
    for (int k = 0; k < 4; k++) {
        int dr = w + (k << 3);
        int r = r0 + dr;
        int ti = 31 + dr - l;
        int vi = dr + l;
        size_t o = ((size_t)n << 17) + ((size_t)r << 9) + s;
        g_Sp0[o] = tile[ti][vi];
        g_Sp1[o] = tile[ti][vi + 1];
    }
}

// ---- fused separable 12-tap conv (col pass then row pass) on a 256xW field ----
template<int W, bool QPER, int CL>
__device__ __forceinline__ void conv_ff(const float* __restrict__ inb,
                                        const float* __restrict__ f,
                                        int r0, int s0, int tid, float (&F)[4]) {
    __shared__ float ti[44][45];
    __shared__ float tc[44][33];
    float fv[12];
#pragma unroll
    for (int k = 0; k < 12; k++) fv[k] = f[k];
    PDL_SYNC();
    constexpr int LSH = (W == 512) ? 9 : 8;
    for (int e = tid; e < 44 * 44; e += 256) {
        int lt = e / 44, ls = e - lt * 44;
        int t = r0 + lt - 6;
        int s = s0 + ls - 6;
        int sr, sc;
        if (QPER) {
            if ((unsigned)t < 256u) { sr = t; sc = s & (W - 1); }
            else { sr = t & 255; sc = (s + (W / 2)) & (W - 1); }
        } else { sr = t & 255; sc = s & (W - 1); }
        ti[lt][ls] = inb[(sr << LSH) + sc];
    }
    __syncthreads();
    for (int e = tid; e < 44 * 32; e += 256) {
        int lt = e >> 5, lo = e & 31;
        float acc = 0.f;
#pragma unroll
        for (int b = 0; b < 12; b++) acc += fv[b] * ti[lt][lo + b + (6 - CL)];
        tc[lt][lo] = acc;
    }
    __syncthreads();
    int w = tid >> 5, l = tid & 31;
#pragma unroll
    for (int k = 0; k < 4; k++) {
        int li = w + (k << 3);
        float acc = 0.f;
#pragma unroll
        for (int a = 0; a < 12; a++) acc += fv[a] * tc[li + a + (6 - CL)][l];
        F[k] = acc;
    }
}

// 6+7) F1 = conv_qper(Sp1) ; Sx0 = (Sp0 - 8*F1)/sqrt2
__global__ void kconvq1(const float* __restrict__ f, int n0) {
    int n = blockIdx.z + n0, r0 = blockIdx.y << 5, s0 = blockIdx.x << 5;
    int tid = threadIdx.x;
    float F[4];
    conv_ff<512, true, 6>(g_Sp1 + ((size_t)n << 17), f, r0, s0, tid, F);
    int w = tid >> 5, l = tid & 31;
    size_t base = ((size_t)n << 17) + s0 + l;
#pragma unroll
    for (int k = 0; k < 4; k++) {
        size_t o = base + ((size_t)(r0 + w + (k << 3)) << 9);
        g_F1[o] = F[k];
        g_Sx0[o] = (g_Sp0[o] - 8.f * F[k]) * RSQ2;
    }
}

// 8+9) F2 = conv_qper(Sx0, shift0) ; Sxx = Sx0 - sqrt2*Sp1 - 8*F2
__global__ void kconvq2(const float* __restrict__ f, int n0) {
    int n = blockIdx.z + n0, r0 = blockIdx.y << 5, s0 = blockIdx.x << 5;
    int tid = threadIdx.x;
    float F[4];
    conv_ff<512, true, 5>(g_Sx0 + ((size_t)n << 17), f, r0, s0, tid, F);
    int w = tid >> 5, l = tid & 31;
    size_t base = ((size_t)n << 17) + s0 + l;
#pragma unroll
    for (int k = 0; k < 4; k++) {
        size_t o = base + ((size_t)(r0 + w + (k << 3)) << 9);
        g_F2[o] = F[k];
        g_Sxx[o] = g_Sx0[o] - SQ2F * g_Sp1[o] - 8.f * F[k];
    }
}

// 10) TILED level-2 quincunx remap.
__global__ void kremap2t(int n0) {
    __shared__ float tile[64][66];
    PDL_SYNC();
    int n = blockIdx.z + n0;
    int i0 = blockIdx.y << 5;
    int j0 = blockIdx.x << 5;
    const float* Sxx = g_Sxx + ((size_t)n << 17);
    int tid = threadIdx.x;
    int w = tid >> 5, l = tid & 31;
    int S = i0 + j0;
    if (S == 224) {
#pragma unroll
        for (int k = 0; k < 4; k++) {
            int i = i0 + w + (k << 3), j = j0 + l;
            int ipj = i + j;
            int u = (j - i + ((ipj >= 256) ? 256 : 0)) & 511;
            int I1 = (ipj + 1) & 255;
            int s1 = (ipj == 255) ? (2 * j + 1) : u;
            size_t o = ((size_t)n << 16) + ((size_t)i << 8) + j;
            g_SP0[o] = Sxx[((ipj & 255) << 9) + u];
            g_SP1[o] = Sxx[(I1 << 9) + s1];
        }
        return;
    }
    int d0 = (S >= 256) ? 256 : 0;
    int Ibase = S & 255;
    int ubase = (j0 - i0 - 31 + d0) & 511;
#pragma unroll
    for (int it = 0; it < 16; it++) {
        int lr = (it << 2) + (tid >> 6);
        int lc = tid & 63;
        tile[lr][lc] = Sxx[((Ibase + lr) << 9) + ((ubase + lc) & 511)];
    }
    __syncthreads();
    int j = j0 + l;
#pragma unroll
    for (int k = 0; k < 4; k++) {
        int di = w + (k << 3);
        int i = i0 + di;
        int lr = di + l;
        int lc = l - di + 31;
        size_t o = ((size_t)n << 16) + ((size_t)i << 8) + j;
        g_SP0[o] = tile[lr][lc];
        g_SP1[o] = tile[lr + 1][lc];
    }
}

// 11+12) G1 = conv_per(SP1) ; Se0 = (SP0 - 16*G1)/sqrt2
__global__ void kconvp1(const float* __restrict__ f, int n0) {
    int n = blockIdx.z + n0, r0 = blockIdx.y << 5, s0 = blockIdx.x << 5;
    int tid = threadIdx.x;
    float F[4];
    conv_ff<256, false, 6>(g_SP1 + ((size_t)n << 16), f, r0, s0, tid, F);
    int w = tid >> 5, l = tid & 31;
    size_t base = ((size_t)n << 16) + s0 + l;
#pragma unroll
    for (int k = 0; k < 4; k++) {
        size_t o = base + ((size_t)(r0 + w + (k << 3)) << 8);
        g_G1[o] = F[k];
        g_Se0[o] = (g_SP0[o] - 16.f * F[k]) * RSQ2;
    }
}

// 13+14) G2 = conv_per(Se0, shift0)
__global__ void kconvp2(const float* __restrict__ f, int n0) {
    int n = blockIdx.z + n0, r0 = blockIdx.y << 5, s0 = blockIdx.x << 5;
    int tid = threadIdx.x;
    float F[4];
    conv_ff<256, false, 5>(g_Se0 + ((size_t)n << 16), f, r0, s0, tid, F);
    int w = tid >> 5, l = tid & 31;
    size_t base = ((size_t)n << 16) + s0 + l;
#pragma unroll
    for (int k = 0; k < 4; k++) {
        size_t o = base + ((size_t)(r0 + w + (k << 3)) << 8);
        g_G2[o] = F[k];
    }
}

// 15) final combine, j-pair vectorized.
__global__ void kfinal(const float* __restrict__ X, float* __restrict__ out,
                       int n0) {
    PDL_SYNC();
    int idx = blockIdx.x * blockDim.x + threadIdx.x + (n0 << 15);
    int n = idx >> 15;
    int rem = idx & 32767;
    int i = rem >> 7, jp = rem & 127;
    int j = jp << 1;

    const float* B  = g_B  + ((size_t)n << 18);
    const float* F1 = g_F1 + ((size_t)n << 17);
    const float* F2 = g_F2 + ((size_t)n << 17);
    size_t gidx = ((size_t)n << 16) + ((size_t)i << 8) + j;
    float2 g1v = *reinterpret_cast<const float2*>(g_G1 + gidx);
    float2 g2v = *reinterpret_cast<const float2*>(g_G2 + gidx);

    int rowE = 2 * i, rowO = 2 * i + 1;
    int xiE = rowE << 9, xiO = rowO << 9;
    int c4 = jp << 2;
    float4 Be = *reinterpret_cast<const float4*>(B + xiE + c4);
    float4 Bo = *reinterpret_cast<const float4*>(B + xiO + c4);
    float  Box = B[xiO + ((c4 + 4) & 511)];

    float K0[2], K1[2], K2[2], K3[2];
#pragma unroll
    for (int jj = 0; jj < 2; jj++) {
        int jv = j + jj;
        int ipj = i + jv;
        int d0 = (ipj >= 256) ? 256 : 0;
        int u  = (jv - i + d0) & 511;
        int r  = ipj & 255;
        int r1 = (ipj + 1) & 255;
        int s1 = (ipj == 255) ? (2 * jv + 1) : u;
        float f1a = F1[(r  << 9) + u];
        float f1b = F1[(r1 << 9) + s1];
        float f2a = F2[(r  << 9) + u];
        float f2b = F2[(r1 << 9) + s1];
        float b00 = jj ? Be.z : Be.x;
        float b01 = jj ? Be.w : Be.y;
        float b10 = jj ? Bo.w : Bo.y;
        float b11 = jj ? Box  : Bo.z;
        float g1 = jj ? g1v.y : g1v.x;
        float g2 = jj ? g2v.y : g2v.x;
        K0[jj] = 0.5f * (b00 + f1a) + g1 * RSQ2;
        K1[jj] = b01 - (f2a + g1) * RSQ2;
        K2[jj] = b10 + f1b - g2;
        K3[jj] = -2.f * b11 + SQ2F * f2b - g2;
    }

    const float* Xn = X + ((size_t)(n * CHN) << 18);
    size_t obase = (size_t)(n * CHN) * 65536 + ((size_t)i << 8) + j;
    int xoxc = (c4 + 4) & 511;
#pragma unroll
    for (int c = 0; c < CHN; c++) {
        const float* Xc = Xn + ((size_t)c << 18);
        float4 Xe = *reinterpret_cast<const float4*>(Xc + xiE + c4);
        float4 Xo = *reinterpret_cast<const float4*>(Xc + xiO + c4);
        float  Xox = Xc[xiO + xoxc];
        size_t o = obase + (size_t)c * 65536;
        *reinterpret_cast<float2*>(out + (size_t)SECSZ * 1 + o) =
            make_float2(-Xo.y + K2[0], -Xo.w + K2[1]);
        *reinterpret_cast<float2*>(out + (size_t)SECSZ * 2 + o) =
            make_float2(0.5f * Xe.x - K0[0], 0.5f * Xe.z - K0[1]);
        *reinterpret_cast<float2*>(out + (size_t)SECSZ * 3 + o) =
            make_float2(2.f * Xo.z + K3[0], 2.f * Xox + K3[1]);
        *reinterpret_cast<float2*>(out + (size_t)SECSZ * 4 + o) =
            make_float2(-Xe.y + K1[0], -Xe.w + K1[1]);
    }
}

// ---------------- PDL launch helper -----------------------------------------
template <typename Kern, typename... Args>
static inline void pdl_launch(Kern kern, dim3 gr, dim3 bl, cudaStream_t st,
                              Args... args) {
    cudaLaunchConfig_t cfg = {};
    cfg.gridDim = gr;
    cfg.blockDim = bl;
    cfg.dynamicSmemBytes = 0;
    cfg.stream = st;
    cudaLaunchAttribute at[1];
    at[0].id = cudaLaunchAttributeProgrammaticStreamSerialization;
    at[0].val.programmaticStreamSerializationAllowed = 1;
    cfg.attrs = at;
    cfg.numAttrs = 1;
    cudaLaunchKernelEx(&cfg, kern, args...);
}

// ---------------- launch: NSTREAM independent batch chains, PDL-chained ----
static void launch_chain(cudaStream_t st, int n0,
                         const float* X, const float* h, const float* g,
                         const float* f, float* out) {
    // stage 1: plain launch (no predecessor in this stream)
    ksumrow<<<NB_PER * HH, 128, 0, st>>>(X, h, n0);
    // stages 2..10: PDL secondaries (each calls cudaGridDependencySynchronize)
    pdl_launch(kpool,    dim3(NB_PER * 256), dim3(256), st, h, out, n0);
    pdl_launch(kBSd,     dim3(NB_PER * 1024), dim3(256), st, g, n0);
    pdl_launch(kremap1t, dim3(16, 8, NB_PER), dim3(256), st, n0);
    pdl_launch(kconvq1,  dim3(16, 8, NB_PER), dim3(256), st, f, n0);
    pdl_launch(kconvq2,  dim3(16, 8, NB_PER), dim3(256), st, f, n0);
    pdl_launch(kremap2t, dim3(8, 8, NB_PER), dim3(256), st, n0);
    pdl_launch(kconvp1,  dim3(8, 8, NB_PER), dim3(256), st, f, n0);
    pdl_launch(kconvp2,  dim3(8, 8, NB_PER), dim3(256), st, f, n0);
    pdl_launch(kfinal,   dim3(NB_PER * 128), dim3(256), st, X, out, n0);
}

extern "C" void kernel_launch(void* const* d_in, const int* in_sizes, int n_in,
                              void* d_out, int out_size) {
    const float* X = (const float*)d_in[0];
    const float* h = (const float*)d_in[1];
    const float* g = (const float*)d_in[2];
    const float* f = (const float*)d_in[3];
    float* out = (float*)d_out;

    // fork from the (captured) default stream
    cudaEventRecord(g_evRoot, 0);
    for (int k = 0; k < NSTREAM; k++)
        cudaStreamWaitEvent(g_s[k], g_evRoot, 0);

    for (int k = 0; k < NSTREAM; k++)
        launch_chain(g_s[k], k * NB_PER, X, h, g, f, out);

    // join back into the default stream
    for (int k = 0; k < NSTREAM; k++) {
        cudaEventRecord(g_evEnd[k], g_s[k]);
        cudaStreamWaitEvent(0, g_evEnd[k], 0);
    }
}